// round 2
// baseline (speedup 1.0000x reference)
#include <cuda_runtime.h>
#include <math.h>

#define SQ 4096
#define DD 1024
#define HH 512
#define TT 20
#define G4H 2048
#define NEGV -10000.0f

// ---------------- static scratch (allocation-free) ----------------
__device__ float g_pre[2][SQ][G4H];    // input projections + bias
__device__ float g_hout[2][SQ][HH];    // hidden states, natural position order
__device__ float g_hx[2][2][HH];       // [parity][dir][H] h exchange buffers
__device__ int   g_flags[2][64];       // per (dir, cta) monotonic step counters
__device__ float g_feats[SQ][TT];      // emission scores

__device__ __forceinline__ int ld_acq(const int* p) {
    int v; asm volatile("ld.acquire.gpu.global.b32 %0, [%1];" : "=r"(v) : "l"(p)); return v;
}
__device__ __forceinline__ void st_rel(int* p, int v) {
    asm volatile("st.release.gpu.global.b32 [%0], %1;" :: "l"(p), "r"(v));
}
__device__ __forceinline__ float sigf(float x) { return 1.0f / (1.0f + expf(-x)); }

// ---------------- kernel 0: per-replay init ----------------
__global__ void init_kernel(const float* __restrict__ h0) {
    int t = threadIdx.x;
    if (t < 2 * HH) g_hx[0][t >> 9][t & (HH - 1)] = h0[t];
    if (t < 128) ((int*)g_flags)[t] = 0;
}

// ---------------- kernel 1: fused gather + input-projection SGEMM ----------------
// g_pre[dir][m][n] = sum_k embed[sent[m]][k] * W_ih[n][k] + b[n]
__global__ __launch_bounds__(256) void gemm_pre_kernel(
    const int* __restrict__ sent, const float* __restrict__ embed,
    const float* __restrict__ Wf, const float* __restrict__ bf,
    const float* __restrict__ Wb, const float* __restrict__ bb)
{
    const int dir = blockIdx.z;
    const float* __restrict__ W    = dir ? Wb : Wf;
    const float* __restrict__ bias = dir ? bb : bf;
    const int n0  = blockIdx.x * 128;
    const int m0  = blockIdx.y * 128;
    const int tid = threadIdx.x;

    __shared__ float As[8][128];
    __shared__ float Bs[8][128];

    const int tx = tid & 15, ty = tid >> 4;
    float acc[8][8];
    #pragma unroll
    for (int i = 0; i < 8; i++)
        #pragma unroll
        for (int j = 0; j < 8; j++) acc[i][j] = 0.f;

    const int lm = tid >> 1;
    const int lk = (tid & 1) * 4;
    const int arow = sent[m0 + lm];
    const float* aptr = embed + (size_t)arow * DD + lk;
    const float* bptr = W + (size_t)(n0 + lm) * DD + lk;

    for (int k0 = 0; k0 < DD; k0 += 8) {
        float4 avv = *(const float4*)(aptr + k0);
        float4 bvv = *(const float4*)(bptr + k0);
        As[lk+0][lm]=avv.x; As[lk+1][lm]=avv.y; As[lk+2][lm]=avv.z; As[lk+3][lm]=avv.w;
        Bs[lk+0][lm]=bvv.x; Bs[lk+1][lm]=bvv.y; Bs[lk+2][lm]=bvv.z; Bs[lk+3][lm]=bvv.w;
        __syncthreads();
        #pragma unroll
        for (int kk = 0; kk < 8; kk++) {
            float4 a0 = *(const float4*)&As[kk][ty*4];
            float4 a1 = *(const float4*)&As[kk][64 + ty*4];
            float4 b0 = *(const float4*)&Bs[kk][tx*4];
            float4 b1 = *(const float4*)&Bs[kk][64 + tx*4];
            float av[8] = {a0.x,a0.y,a0.z,a0.w,a1.x,a1.y,a1.z,a1.w};
            float bv[8] = {b0.x,b0.y,b0.z,b0.w,b1.x,b1.y,b1.z,b1.w};
            #pragma unroll
            for (int i = 0; i < 8; i++)
                #pragma unroll
                for (int j = 0; j < 8; j++)
                    acc[i][j] += av[i] * bv[j];
        }
        __syncthreads();
    }

    #pragma unroll
    for (int i = 0; i < 8; i++) {
        int m = m0 + ((i < 4) ? (ty*4 + i) : (64 + ty*4 + i - 4));
        #pragma unroll
        for (int j = 0; j < 8; j++) {
            int n = n0 + ((j < 4) ? (tx*4 + j) : (64 + tx*4 + j - 4));
            acc[i][j] += bias[n];
        }
        float4 o0 = {acc[i][0], acc[i][1], acc[i][2], acc[i][3]};
        float4 o1 = {acc[i][4], acc[i][5], acc[i][6], acc[i][7]};
        *(float4*)&g_pre[dir][m][n0 + tx*4]      = o0;
        *(float4*)&g_pre[dir][m][n0 + 64 + tx*4] = o1;
    }
}

// ---------------- kernel 2: persistent bidirectional LSTM ----------------
// 128 CTAs: dir = bid>>6, g = bid&63. Warp w owns hidden unit j = 8g+w,
// gate rows {j, H+j, 2H+j, 3H+j}; W_hh slice lives in registers.
__global__ __launch_bounds__(256, 1) void lstm_kernel(
    const float* __restrict__ Whf, const float* __restrict__ Whb,
    const float* __restrict__ c0)
{
    const int bx  = blockIdx.x;
    const int dir = bx >> 6;
    const int g   = bx & 63;
    const int tid = threadIdx.x;
    const int w   = tid >> 5, l = tid & 31;
    const int j   = g * 8 + w;
    const float* __restrict__ Whh = dir ? Whb : Whf;

    // lane l holds k = 128*i + 4*l .. +3 for i<4, per gate row r
    float4 wr[4][4];
    #pragma unroll
    for (int r = 0; r < 4; r++) {
        const float* wrow = Whh + (size_t)(r * HH + j) * HH;
        #pragma unroll
        for (int i = 0; i < 4; i++)
            wr[r][i] = *(const float4*)(wrow + i * 128 + l * 4);
    }

    float c = 0.f;
    if (l == 0) c = c0[dir * HH + j];

    int* myflags = &g_flags[dir][0];

    for (int t = 0; t < SQ; ++t) {
        const int m = dir ? (SQ - 1 - t) : t;

        // prefetch input-projection contributions (hidden under the spin)
        float pre = 0.f;
        if (l < 4) pre = g_pre[dir][m][l * HH + j];

        if (tid < 64) {
            while (ld_acq(&myflags[tid]) < t) { }
        }
        __syncthreads();

        // load h_{t-1} (bypass L1: written by remote SMs)
        const float4* hp = (const float4*)(g_hx[t & 1][dir]);
        float4 hv[4];
        #pragma unroll
        for (int i = 0; i < 4; i++) hv[i] = __ldcg(hp + i * 32 + l);

        float p[4] = {0.f, 0.f, 0.f, 0.f};
        if (l < 4) p[l] = pre;   // NOTE: only lane r contributes pre to row r
        #pragma unroll
        for (int r = 0; r < 4; r++) {
            #pragma unroll
            for (int i = 0; i < 4; i++) {
                p[r] += wr[r][i].x * hv[i].x;
                p[r] += wr[r][i].y * hv[i].y;
                p[r] += wr[r][i].z * hv[i].z;
                p[r] += wr[r][i].w * hv[i].w;
            }
        }
        // hmm: pre must land in the right row regardless of lane — fix below
        // (p[l]=pre puts row-l's pre on lane l; after the full butterfly sum
        //  every row's total includes exactly one lane's pre. Correct.)
        #pragma unroll
        for (int off = 16; off > 0; off >>= 1) {
            p[0] += __shfl_xor_sync(0xffffffffu, p[0], off);
            p[1] += __shfl_xor_sync(0xffffffffu, p[1], off);
            p[2] += __shfl_xor_sync(0xffffffffu, p[2], off);
            p[3] += __shfl_xor_sync(0xffffffffu, p[3], off);
        }

        if (l == 0) {
            float gi = p[0], gf = p[1], gg = p[2], go = p[3];
            c = sigf(gf) * c + sigf(gi) * tanhf(gg);
            float h = sigf(go) * tanhf(c);
            g_hout[dir][m][j] = h;
            g_hx[(t + 1) & 1][dir][j] = h;
        }
        __syncthreads();
        if (tid == 0) {
            __threadfence();
            st_rel(&g_flags[dir][g], t + 1);
        }
    }
}

// ---------------- kernel 3: tag projection ----------------
// feats[m][t] = concat(h_f[m], h_b[m]) . W_tag[t] + b_tag[t]
__global__ void feats_kernel(const float* __restrict__ Wtag,
                             const float* __restrict__ btag)
{
    const int m = blockIdx.x;
    const int tid = threadIdx.x;         // 160 threads: 20 tags x 8 subs
    const int tag = tid >> 3, sub = tid & 7;
    const float* x = (sub < 4) ? &g_hout[0][m][0] : &g_hout[1][m][0];
    const int off = (sub & 3) * 128;
    const float* wp = Wtag + (size_t)tag * (2 * HH) + sub * 128;

    float s = 0.f;
    #pragma unroll 8
    for (int i = 0; i < 32; i++) {
        float4 xv = *(const float4*)(x + off + i * 4);
        float4 wv = *(const float4*)(wp + i * 4);
        s += xv.x * wv.x + xv.y * wv.y + xv.z * wv.z + xv.w * wv.w;
    }
    s += __shfl_xor_sync(0xffffffffu, s, 1);
    s += __shfl_xor_sync(0xffffffffu, s, 2);
    s += __shfl_xor_sync(0xffffffffu, s, 4);
    if (sub == 0) g_feats[m][tag] = s + btag[tag];
}

// ---------------- kernel 4: Viterbi + backtrace ----------------
extern __shared__ char sm_raw[];

__global__ void viterbi_kernel(const float* __restrict__ trans,
                               const int* __restrict__ startp,
                               const int* __restrict__ stopp,
                               float* __restrict__ out)
{
    char*  bp   = sm_raw;                         // [SQ][TT] backpointers
    float* fv   = (float*)(sm_raw + SQ * TT);     // [32]
    float* term = fv + 32;                        // [32]
    const int n = threadIdx.x;                    // lane = next-tag
    const int start = *startp;
    const int stop  = *stopp;

    float trn[TT];
    if (n < TT) {
        #pragma unroll
        for (int p = 0; p < TT; p++) trn[p] = trans[n * TT + p];
        fv[n] = (n == start) ? 0.f : NEGV;
    }
    __syncwarp();

    float ft = (n < TT) ? g_feats[0][n] : 0.f;

    for (int t = 0; t < SQ; ++t) {
        float ftn = (n < TT && t + 1 < SQ) ? g_feats[t + 1][n] : 0.f;

        float fvn = 0.f; int arg = 0; float best = 0.f;
        if (n < TT) {
            float s[TT];
            #pragma unroll
            for (int p = 0; p < TT; p++) s[p] = fv[p] + trn[p];
            // 4 parallel chains, then tree combine; first-max tie semantics
            float b0 = s[0];  int a0 = 0;
            #pragma unroll
            for (int p = 1; p < 5; p++)   if (s[p] > b0) { b0 = s[p]; a0 = p; }
            float b1 = s[5];  int a1 = 5;
            #pragma unroll
            for (int p = 6; p < 10; p++)  if (s[p] > b1) { b1 = s[p]; a1 = p; }
            float b2 = s[10]; int a2 = 10;
            #pragma unroll
            for (int p = 11; p < 15; p++) if (s[p] > b2) { b2 = s[p]; a2 = p; }
            float b3 = s[15]; int a3 = 15;
            #pragma unroll
            for (int p = 16; p < 20; p++) if (s[p] > b3) { b3 = s[p]; a3 = p; }
            if (b1 > b0) { b0 = b1; a0 = a1; }
            if (b3 > b2) { b2 = b3; a2 = a3; }
            if (b2 > b0) { b0 = b2; a0 = a2; }
            best = b0; arg = a0;
            fvn = best + ft;
            bp[t * TT + n] = (char)arg;
        }
        __syncwarp();
        if (n < TT) fv[n] = fvn;
        __syncwarp();
        ft = ftn;
    }

    if (n < TT) term[n] = fv[n] + trans[stop * TT + n];
    __syncwarp();

    if (n == 0) {
        float best = term[0]; int bt = 0;
        #pragma unroll
        for (int p = 1; p < TT; p++) if (term[p] > best) { best = term[p]; bt = p; }
        out[0] = best;
        int tag = bt;
        out[SQ] = (float)bt;                      // out[1 + (SQ-1)]
        for (int t = SQ - 1; t >= 1; --t) {
            tag = bp[t * TT + tag];
            out[t] = (float)tag;                  // out[1 + (t-1)]
        }
    }
}

// ---------------- launcher ----------------
extern "C" void kernel_launch(void* const* d_in, const int* in_sizes, int n_in,
                              void* d_out, int out_size) {
    const int*   sent  = (const int*)  d_in[0];
    const float* embed = (const float*)d_in[1];
    const float* Wihf  = (const float*)d_in[2];
    const float* Whhf  = (const float*)d_in[3];
    const float* bf    = (const float*)d_in[4];
    const float* Wihb  = (const float*)d_in[5];
    const float* Whhb  = (const float*)d_in[6];
    const float* bb    = (const float*)d_in[7];
    const float* h0    = (const float*)d_in[8];
    const float* c0    = (const float*)d_in[9];
    const float* Wtag  = (const float*)d_in[10];
    const float* btag  = (const float*)d_in[11];
    const float* trans = (const float*)d_in[12];
    const int*   start = (const int*)  d_in[13];
    const int*   stop  = (const int*)  d_in[14];
    float* out = (float*)d_out;

    const int vit_smem = SQ * TT + 64 * 4 + 256;   // 82432 B
    cudaFuncSetAttribute(viterbi_kernel,
                         cudaFuncAttributeMaxDynamicSharedMemorySize, vit_smem);

    init_kernel<<<1, 1024>>>(h0);
    gemm_pre_kernel<<<dim3(16, 32, 2), 256>>>(sent, embed, Wihf, bf, Wihb, bb);
    lstm_kernel<<<128, 256>>>(Whhf, Whhb, c0);
    feats_kernel<<<SQ, 160>>>(Wtag, btag);
    viterbi_kernel<<<1, 32, vit_smem>>>(trans, start, stop, out);
}

// round 3
// speedup vs baseline: 2.9203x; 2.9203x over previous
#include <cuda_runtime.h>
#include <math.h>

#define SQ 4096
#define DD 1024
#define HH 512
#define TT 20
#define G4H 2048
#define NEGV -10000.0f

// ---------------- static scratch (allocation-free) ----------------
__device__ float g_pre[2][SQ][G4H];     // input projections + bias
__device__ float g_hout[2][SQ][HH];     // hidden states, natural position order
__device__ uint4 g_hp[2][2][HH / 2];    // [parity][dir][e]: {h(2e),tag, h(2e+1),tag}
__device__ float g_feats[SQ][TT];       // emission scores

__device__ __forceinline__ float sigf(float x) { return 1.0f / (1.0f + expf(-x)); }

// ---------------- kernel 0: per-replay init ----------------
__global__ void init_kernel(const float* __restrict__ h0) {
    int t = threadIdx.x;                 // 1024 threads
    int dir = t >> 9, k = t & (HH - 1);
    uint2* even = (uint2*)&g_hp[0][dir][0];
    uint2* odd  = (uint2*)&g_hp[1][dir][0];
    even[k] = make_uint2(__float_as_uint(h0[dir * HH + k]), 0u);   // h_0, tag 0
    odd[k]  = make_uint2(0u, 0xFFFFFFFFu);                         // poison
}

__global__ void dummy_kernel() {}

// ---------------- kernel 1: fused gather + input-projection SGEMM ----------------
__global__ __launch_bounds__(256) void gemm_pre_kernel(
    const int* __restrict__ sent, const float* __restrict__ embed,
    const float* __restrict__ Wf, const float* __restrict__ bf,
    const float* __restrict__ Wb, const float* __restrict__ bb)
{
    const int dir = blockIdx.z;
    const float* __restrict__ W    = dir ? Wb : Wf;
    const float* __restrict__ bias = dir ? bb : bf;
    const int n0  = blockIdx.x * 128;
    const int m0  = blockIdx.y * 128;
    const int tid = threadIdx.x;

    __shared__ float As[8][128];
    __shared__ float Bs[8][128];

    const int tx = tid & 15, ty = tid >> 4;
    float acc[8][8];
    #pragma unroll
    for (int i = 0; i < 8; i++)
        #pragma unroll
        for (int j = 0; j < 8; j++) acc[i][j] = 0.f;

    const int lm = tid >> 1;
    const int lk = (tid & 1) * 4;
    const int arow = sent[m0 + lm];
    const float* aptr = embed + (size_t)arow * DD + lk;
    const float* bptr = W + (size_t)(n0 + lm) * DD + lk;

    float4 an = *(const float4*)(aptr);
    float4 bn = *(const float4*)(bptr);

    for (int k0 = 0; k0 < DD; k0 += 8) {
        As[lk+0][lm]=an.x; As[lk+1][lm]=an.y; As[lk+2][lm]=an.z; As[lk+3][lm]=an.w;
        Bs[lk+0][lm]=bn.x; Bs[lk+1][lm]=bn.y; Bs[lk+2][lm]=bn.z; Bs[lk+3][lm]=bn.w;
        __syncthreads();
        if (k0 + 8 < DD) {
            an = *(const float4*)(aptr + k0 + 8);
            bn = *(const float4*)(bptr + k0 + 8);
        }
        #pragma unroll
        for (int kk = 0; kk < 8; kk++) {
            float4 a0 = *(const float4*)&As[kk][ty*4];
            float4 a1 = *(const float4*)&As[kk][64 + ty*4];
            float4 b0 = *(const float4*)&Bs[kk][tx*4];
            float4 b1 = *(const float4*)&Bs[kk][64 + tx*4];
            float av[8] = {a0.x,a0.y,a0.z,a0.w,a1.x,a1.y,a1.z,a1.w};
            float bv[8] = {b0.x,b0.y,b0.z,b0.w,b1.x,b1.y,b1.z,b1.w};
            #pragma unroll
            for (int i = 0; i < 8; i++)
                #pragma unroll
                for (int j = 0; j < 8; j++)
                    acc[i][j] += av[i] * bv[j];
        }
        __syncthreads();
    }

    #pragma unroll
    for (int i = 0; i < 8; i++) {
        int m = m0 + ((i < 4) ? (ty*4 + i) : (64 + ty*4 + i - 4));
        #pragma unroll
        for (int j = 0; j < 8; j++) {
            int n = n0 + ((j < 4) ? (tx*4 + j) : (64 + tx*4 + j - 4));
            acc[i][j] += bias[n];
        }
        float4 o0 = {acc[i][0], acc[i][1], acc[i][2], acc[i][3]};
        float4 o1 = {acc[i][4], acc[i][5], acc[i][6], acc[i][7]};
        *(float4*)&g_pre[dir][m][n0 + tx*4]      = o0;
        *(float4*)&g_pre[dir][m][n0 + 64 + tx*4] = o1;
    }
}

// ---------------- kernel 2: persistent bidirectional LSTM ----------------
// 128 CTAs: dir = bid>>6, g = bid&63. Warp w owns hidden unit j = 8g+w,
// gate rows {j, H+j, 2H+j, 3H+j}; W_hh slice register-resident.
// h exchange: tagged 8-byte (h, step) pairs through L2, one RTT per step.
__global__ __launch_bounds__(256, 1) void lstm_kernel(
    const float* __restrict__ Whf, const float* __restrict__ Whb,
    const float* __restrict__ c0)
{
    const int bx  = blockIdx.x;
    const int dir = bx >> 6;
    const int g   = bx & 63;
    const int tid = threadIdx.x;
    const int w   = tid >> 5, l = tid & 31;
    const int j   = g * 8 + w;
    const float* __restrict__ Whh = dir ? Whb : Whf;

    // lane l holds W[r][k], k = 128*i + 4*l .. +3, i<4, per gate row r
    float4 wr[4][4];
    #pragma unroll
    for (int r = 0; r < 4; r++) {
        const float* wrow = Whh + (size_t)(r * HH + j) * HH;
        #pragma unroll
        for (int i = 0; i < 4; i++)
            wr[r][i] = *(const float4*)(wrow + i * 128 + l * 4);
    }

    float c = 0.f;
    if (l == 0) c = c0[dir * HH + j];

    __shared__ float hsm[2][HH];        // parity double buffer

    for (int t = 0; t < SQ; ++t) {
        const int m = dir ? (SQ - 1 - t) : t;
        const int par = t & 1;

        // prefetch input-projection contribution (hidden under the poll)
        float pre = 0.f;
        if (l < 4) pre = g_pre[dir][m][l * HH + j];

        // cooperative poll: thread tid owns h[2*tid], h[2*tid+1]
        {
            const uint4* pp = &g_hp[par][dir][tid];
            uint4 v = __ldcg(pp);
            while (v.y != (unsigned)t || v.w != (unsigned)t) v = __ldcg(pp);
            hsm[par][2 * tid]     = __uint_as_float(v.x);
            hsm[par][2 * tid + 1] = __uint_as_float(v.z);
        }
        __syncthreads();

        float4 hv[4];
        #pragma unroll
        for (int i = 0; i < 4; i++)
            hv[i] = *(const float4*)&hsm[par][i * 128 + l * 4];

        float p[4] = {0.f, 0.f, 0.f, 0.f};
        if (l < 4) p[l] = pre;          // row-l pre rides on lane l
        #pragma unroll
        for (int r = 0; r < 4; r++) {
            #pragma unroll
            for (int i = 0; i < 4; i++) {
                p[r] += wr[r][i].x * hv[i].x;
                p[r] += wr[r][i].y * hv[i].y;
                p[r] += wr[r][i].z * hv[i].z;
                p[r] += wr[r][i].w * hv[i].w;
            }
        }
        #pragma unroll
        for (int off = 16; off > 0; off >>= 1) {
            p[0] += __shfl_xor_sync(0xffffffffu, p[0], off);
            p[1] += __shfl_xor_sync(0xffffffffu, p[1], off);
            p[2] += __shfl_xor_sync(0xffffffffu, p[2], off);
            p[3] += __shfl_xor_sync(0xffffffffu, p[3], off);
        }

        // activations in parallel on lanes 0..3 (all lanes hold identical p[])
        float pv  = p[l & 3];
        float act = ((l & 3) == 2) ? tanhf(pv) : sigf(pv);
        float ai = __shfl_sync(0xffffffffu, act, 0);
        float af = __shfl_sync(0xffffffffu, act, 1);
        float ag = __shfl_sync(0xffffffffu, act, 2);
        float ao = __shfl_sync(0xffffffffu, act, 3);

        if (l == 0) {
            c = af * c + ai * ag;
            float h = ao * tanhf(c);
            g_hout[dir][m][j] = h;
            uint2* dst = (uint2*)&g_hp[(t + 1) & 1][dir][0];
            __stcg(&dst[j], make_uint2(__float_as_uint(h), (unsigned)(t + 1)));
        }
        // no trailing sync needed: parity double buffer + poll ordering
    }
}

// ---------------- kernel 3: tag projection (8 positions per block) ----------------
__global__ void feats_kernel(const float* __restrict__ Wtag,
                             const float* __restrict__ btag)
{
    const int m0 = blockIdx.x * 8;
    const int tid = threadIdx.x;         // 160 threads: 20 tags x 8 subs
    const int tag = tid >> 3, sub = tid & 7;
    const float* xbase = (sub < 4) ? &g_hout[0][0][0] : &g_hout[1][0][0];
    const int off = (sub & 3) * 128;
    const float* wp = Wtag + (size_t)tag * (2 * HH) + sub * 128;

    float s[8];
    #pragma unroll
    for (int mm = 0; mm < 8; mm++) s[mm] = 0.f;

    for (int i = 0; i < 32; i++) {
        float4 wv = *(const float4*)(wp + i * 4);
        #pragma unroll
        for (int mm = 0; mm < 8; mm++) {
            float4 xv = *(const float4*)(xbase + (size_t)(m0 + mm) * HH + off + i * 4);
            s[mm] += xv.x * wv.x + xv.y * wv.y + xv.z * wv.z + xv.w * wv.w;
        }
    }
    #pragma unroll
    for (int mm = 0; mm < 8; mm++) {
        s[mm] += __shfl_xor_sync(0xffffffffu, s[mm], 1);
        s[mm] += __shfl_xor_sync(0xffffffffu, s[mm], 2);
        s[mm] += __shfl_xor_sync(0xffffffffu, s[mm], 4);
    }
    if (sub == 0) {
        float b = btag[tag];
        #pragma unroll
        for (int mm = 0; mm < 8; mm++) g_feats[m0 + mm][tag] = s[mm] + b;
    }
}

// ---------------- kernel 4: Viterbi + backtrace ----------------
extern __shared__ char sm_raw[];

__global__ void viterbi_kernel(const float* __restrict__ trans,
                               const int* __restrict__ startp,
                               const int* __restrict__ stopp,
                               float* __restrict__ out)
{
    char*  bp   = sm_raw;                         // [SQ][TT] backpointers
    float* fv   = (float*)(sm_raw + SQ * TT);     // [32]
    float* term = fv + 32;                        // [32]
    const int n = threadIdx.x;                    // lane = next-tag
    const int start = *startp;
    const int stop  = *stopp;

    float trn[TT];
    if (n < TT) {
        #pragma unroll
        for (int p = 0; p < TT; p++) trn[p] = trans[n * TT + p];
        fv[n] = (n == start) ? 0.f : NEGV;
    }
    __syncwarp();

    float ft = (n < TT) ? g_feats[0][n] : 0.f;

    for (int t = 0; t < SQ; ++t) {
        float ftn = (n < TT && t + 1 < SQ) ? g_feats[t + 1][n] : 0.f;

        float fvn = 0.f;
        if (n < TT) {
            float s[TT];
            #pragma unroll
            for (int p = 0; p < TT; p++) s[p] = fv[p] + trn[p];
            float b0 = s[0];  int a0 = 0;
            #pragma unroll
            for (int p = 1; p < 5; p++)   if (s[p] > b0) { b0 = s[p]; a0 = p; }
            float b1 = s[5];  int a1 = 5;
            #pragma unroll
            for (int p = 6; p < 10; p++)  if (s[p] > b1) { b1 = s[p]; a1 = p; }
            float b2 = s[10]; int a2 = 10;
            #pragma unroll
            for (int p = 11; p < 15; p++) if (s[p] > b2) { b2 = s[p]; a2 = p; }
            float b3 = s[15]; int a3 = 15;
            #pragma unroll
            for (int p = 16; p < 20; p++) if (s[p] > b3) { b3 = s[p]; a3 = p; }
            if (b1 > b0) { b0 = b1; a0 = a1; }
            if (b3 > b2) { b2 = b3; a2 = a3; }
            if (b2 > b0) { b0 = b2; a0 = a2; }
            fvn = b0 + ft;
            bp[t * TT + n] = (char)a0;
        }
        __syncwarp();
        if (n < TT) fv[n] = fvn;
        __syncwarp();
        ft = ftn;
    }

    if (n < TT) term[n] = fv[n] + trans[stop * TT + n];
    __syncwarp();

    if (n == 0) {
        float best = term[0]; int bt = 0;
        #pragma unroll
        for (int p = 1; p < TT; p++) if (term[p] > best) { best = term[p]; bt = p; }
        out[0] = best;
        int tag = bt;
        out[SQ] = (float)bt;
        for (int t = SQ - 1; t >= 1; --t) {
            tag = bp[t * TT + tag];
            out[t] = (float)tag;
        }
    }
}

// ---------------- launcher ----------------
extern "C" void kernel_launch(void* const* d_in, const int* in_sizes, int n_in,
                              void* d_out, int out_size) {
    const int*   sent  = (const int*)  d_in[0];
    const float* embed = (const float*)d_in[1];
    const float* Wihf  = (const float*)d_in[2];
    const float* Whhf  = (const float*)d_in[3];
    const float* bf    = (const float*)d_in[4];
    const float* Wihb  = (const float*)d_in[5];
    const float* Whhb  = (const float*)d_in[6];
    const float* bb    = (const float*)d_in[7];
    const float* h0    = (const float*)d_in[8];
    const float* c0    = (const float*)d_in[9];
    const float* Wtag  = (const float*)d_in[10];
    const float* btag  = (const float*)d_in[11];
    const float* trans = (const float*)d_in[12];
    const int*   start = (const int*)  d_in[13];
    const int*   stop  = (const int*)  d_in[14];
    float* out = (float*)d_out;

    const int vit_smem = SQ * TT + 64 * 4 + 256;   // 82432 B
    cudaFuncSetAttribute(viterbi_kernel,
                         cudaFuncAttributeMaxDynamicSharedMemorySize, vit_smem);

    init_kernel<<<1, 1024>>>(h0);
    gemm_pre_kernel<<<dim3(16, 32, 2), 256>>>(sent, embed, Wihf, bf, Wihb, bb);
    dummy_kernel<<<1, 1>>>();
    lstm_kernel<<<128, 256>>>(Whhf, Whhb, c0);
    feats_kernel<<<SQ / 8, 160>>>(Wtag, btag);
    viterbi_kernel<<<1, 32, vit_smem>>>(trans, start, stop, out);
}